// round 17
// baseline (speedup 1.0000x reference)
#include <cuda_runtime.h>
#include <cuda_fp16.h>

#define VOCAB   50257
#define DIM     128
#define BATCH   32
#define M_SLOTS 512
#define S_TOK   6
#define T_TREE  128
#define L_TOK   64
#define SLOTS   (M_SLOTS + T_TREE)        // 640
#define TABN    ((size_t)VOCAB * DIM)     // floats per table
#define CN      (3 * TABN)

// gather decomposition: tree slot = 1 halfwarp x 64 tokens (no smem);
// story = 2 slots per halfwarp
#define TREE_BLK_TAB  (BATCH * T_TREE / 16)    // 256 blocks per table
#define STORY_BLK_TAB (BATCH * M_SLOTS / 32)   // 512 blocks per table
#define GBLK_TAB      (TREE_BLK_TAB + STORY_BLK_TAB)   // 768
#define CB_TAB        ((int)((TABN / 8 + 255) / 256))  // 3142 convert blocks
#define HOP_T   512
#define HW_HOP  (HOP_T / 16)              // 32 halfwarps per hop block
#define SL_HW   (SLOTS / HW_HOP)          // 20 slots per halfwarp

// fp16 tables 1..3 (38.6 MB) and fp16 slot memories (15.7 MB)
__device__ __align__(16) __half g_Ch[CN];
__device__ __align__(16) __half g_Mh[(size_t)3 * BATCH * SLOTS * DIM];

__device__ __forceinline__ float warp_max(float v) {
    #pragma unroll
    for (int o = 16; o; o >>= 1) v = fmaxf(v, __shfl_xor_sync(0xffffffffu, v, o));
    return v;
}
__device__ __forceinline__ float warp_sum(float v) {
    #pragma unroll
    for (int o = 16; o; o >>= 1) v += __shfl_xor_sync(0xffffffffu, v, o);
    return v;
}
__device__ __forceinline__ float hw_sum(float v) {
    #pragma unroll
    for (int o = 8; o; o >>= 1) v += __shfl_xor_sync(0xffffffffu, v, o);
    return v;
}
__device__ __forceinline__ void acc8(float4& lo, float4& hi, uint4 v) {
    float2 f;
    f = __half22float2(*reinterpret_cast<__half2*>(&v.x)); lo.x += f.x; lo.y += f.y;
    f = __half22float2(*reinterpret_cast<__half2*>(&v.y)); lo.z += f.x; lo.w += f.y;
    f = __half22float2(*reinterpret_cast<__half2*>(&v.z)); hi.x += f.x; hi.y += f.y;
    f = __half22float2(*reinterpret_cast<__half2*>(&v.w)); hi.z += f.x; hi.w += f.y;
}
__device__ __forceinline__ uint4 hadd_u4(uint4 a, uint4 b) {
    uint4 r;
    *reinterpret_cast<__half2*>(&r.x) =
        __hadd2(*reinterpret_cast<__half2*>(&a.x), *reinterpret_cast<__half2*>(&b.x));
    *reinterpret_cast<__half2*>(&r.y) =
        __hadd2(*reinterpret_cast<__half2*>(&a.y), *reinterpret_cast<__half2*>(&b.y));
    *reinterpret_cast<__half2*>(&r.z) =
        __hadd2(*reinterpret_cast<__half2*>(&a.z), *reinterpret_cast<__half2*>(&b.z));
    *reinterpret_cast<__half2*>(&r.w) =
        __hadd2(*reinterpret_cast<__half2*>(&a.w), *reinterpret_cast<__half2*>(&b.w));
    return r;
}
__device__ __forceinline__ uint4 pack8(float4 lo, float4 hi) {
    union { __half2 h[4]; uint4 u; } cv;
    cv.h[0] = __floats2half2_rn(lo.x, lo.y);
    cv.h[1] = __floats2half2_rn(lo.z, lo.w);
    cv.h[2] = __floats2half2_rn(hi.x, hi.y);
    cv.h[3] = __floats2half2_rn(hi.z, hi.w);
    return cv.u;
}
__device__ __forceinline__ float dot8(uint4 v, const float* __restrict__ u) {
    float2 f; float s;
    f = __half22float2(*reinterpret_cast<__half2*>(&v.x)); s  = f.x * u[0] + f.y * u[1];
    f = __half22float2(*reinterpret_cast<__half2*>(&v.y)); s += f.x * u[2] + f.y * u[3];
    f = __half22float2(*reinterpret_cast<__half2*>(&v.z)); s += f.x * u[4] + f.y * u[5];
    f = __half22float2(*reinterpret_cast<__half2*>(&v.w)); s += f.x * u[6] + f.y * u[7];
    return s;
}
__device__ __forceinline__ void add4(float4& a, float4 b) {
    a.x += b.x; a.y += b.y; a.z += b.z; a.w += b.w;
}

// ---------------------------------------------------------------------------
// convert ONE table (tab -> source table tab+1) to fp16.
// ---------------------------------------------------------------------------
__global__ void __launch_bounds__(256) convert_kernel(const float* __restrict__ C,
                                                      int tab)
{
    const size_t i = ((size_t)blockIdx.x * 256 + threadIdx.x) * 8;
    if (i >= TABN) return;
    const float4* src =
        reinterpret_cast<const float4*>(C + (size_t)(tab + 1) * TABN + i);
    float4 a = __ldcs(src);
    float4 b = __ldcs(src + 1);
    union { __half2 h[4]; uint4 u; } cv;
    cv.h[0] = __floats2half2_rn(a.x, a.y);
    cv.h[1] = __floats2half2_rn(a.z, a.w);
    cv.h[2] = __floats2half2_rn(b.x, b.y);
    cv.h[3] = __floats2half2_rn(b.z, b.w);
    *reinterpret_cast<uint4*>(g_Ch + (size_t)tab * TABN + i) = cv.u;
}

// ---------------------------------------------------------------------------
// gather ONE table (R16 shape, occ-5). Tree: 1 halfwarp x 64 tokens.
// Story: halfwarp per 2 slots.
// ---------------------------------------------------------------------------
__global__ void __launch_bounds__(256, 5) gather_kernel(
    const int* __restrict__ story, const int* __restrict__ kb, int tab)
{
    const int hw = threadIdx.x >> 4;
    const int hl = threadIdx.x & 15;
    const int r  = blockIdx.x;

    const __half* __restrict__ Ct = g_Ch + (size_t)tab * TABN;

    if (r < TREE_BLK_TAB) {
        const int unit = r * 16 + hw;
        const int b    = unit / T_TREE;
        const int tr   = unit % T_TREE;

        const int4* __restrict__ toks4 =
            reinterpret_cast<const int4*>(kb + ((size_t)b * T_TREE + tr) * L_TOK);

        float4 loA = make_float4(0.f, 0.f, 0.f, 0.f), hiA = loA;
        float4 loB = loA, hiB = loA;

        #pragma unroll
        for (int g = 0; g < 8; ++g) {
            int4 i0 = toks4[2 * g];
            int4 i1 = toks4[2 * g + 1];
            uint4 v0 = reinterpret_cast<const uint4*>(Ct + (size_t)i0.x * DIM)[hl];
            uint4 v1 = reinterpret_cast<const uint4*>(Ct + (size_t)i0.y * DIM)[hl];
            uint4 v2 = reinterpret_cast<const uint4*>(Ct + (size_t)i0.z * DIM)[hl];
            uint4 v3 = reinterpret_cast<const uint4*>(Ct + (size_t)i0.w * DIM)[hl];
            uint4 v4 = reinterpret_cast<const uint4*>(Ct + (size_t)i1.x * DIM)[hl];
            uint4 v5 = reinterpret_cast<const uint4*>(Ct + (size_t)i1.y * DIM)[hl];
            uint4 v6 = reinterpret_cast<const uint4*>(Ct + (size_t)i1.z * DIM)[hl];
            uint4 v7 = reinterpret_cast<const uint4*>(Ct + (size_t)i1.w * DIM)[hl];
            acc8(loA, hiA, hadd_u4(v0, v1));
            acc8(loB, hiB, hadd_u4(v2, v3));
            acc8(loA, hiA, hadd_u4(v4, v5));
            acc8(loB, hiB, hadd_u4(v6, v7));
        }
        add4(loA, loB); add4(hiA, hiB);

        const int slot = M_SLOTS + tr;
        reinterpret_cast<uint4*>(
            g_Mh + ((size_t)(tab * BATCH + b) * SLOTS + slot) * DIM)[hl] =
            pack8(loA, hiA);
    } else {
        const int pair = (r - TREE_BLK_TAB) * 16 + hw;
        const int b    = pair / (M_SLOTS / 2);
        const int s0   = (pair % (M_SLOTS / 2)) * 2;

        const int* t0p = story + ((size_t)b * M_SLOTS + s0) * S_TOK;
        int tka[S_TOK], tkb[S_TOK];
        #pragma unroll
        for (int j = 0; j < S_TOK; ++j) { tka[j] = t0p[j]; tkb[j] = t0p[S_TOK + j]; }

        float4 loA = make_float4(0.f, 0.f, 0.f, 0.f), hiA = loA;
        float4 loB = loA, hiB = loA;
        #pragma unroll
        for (int j = 0; j < S_TOK; ++j) {
            uint4 va = reinterpret_cast<const uint4*>(Ct + (size_t)tka[j] * DIM)[hl];
            uint4 vb = reinterpret_cast<const uint4*>(Ct + (size_t)tkb[j] * DIM)[hl];
            acc8(loA, hiA, va);
            acc8(loB, hiB, vb);
        }
        uint4* dst = reinterpret_cast<uint4*>(
            g_Mh + ((size_t)(tab * BATCH + b) * SLOTS + s0) * DIM);
        dst[hl]      = pack8(loA, hiA);
        dst[16 + hl] = pack8(loB, hiB);
    }
}

// ---------------------------------------------------------------------------
// hops: whole 3-hop chain, one block per batch element (unchanged).
// ---------------------------------------------------------------------------
__global__ void __launch_bounds__(HOP_T) hops_kernel(float* __restrict__ out)
{
    __shared__ float s_score[SLOTS];
    __shared__ float s_part[HW_HOP][DIM];
    __shared__ float s_u[DIM];
    __shared__ float s_red[16];

    const int b    = blockIdx.x;
    const int tid  = threadIdx.x;
    const int w    = tid >> 5;
    const int lane = tid & 31;
    const int hw   = tid >> 4;
    const int hl   = tid & 15;

    const __half* __restrict__ M1 = g_Mh + (size_t)(0 * BATCH + b) * SLOTS * DIM;
    const __half* __restrict__ M2 = g_Mh + (size_t)(1 * BATCH + b) * SLOTS * DIM;
    const __half* __restrict__ M3 = g_Mh + (size_t)(2 * BATCH + b) * SLOTS * DIM;

    // u1 = mean over slots of M1
    {
        float4 lo = make_float4(0.f, 0.f, 0.f, 0.f), hi = lo;
        #pragma unroll 5
        for (int k = 0; k < SL_HW; ++k) {
            uint4 v = reinterpret_cast<const uint4*>(
                M1 + (size_t)(hw * SL_HW + k) * DIM)[hl];
            acc8(lo, hi, v);
        }
        float* p = &s_part[hw][hl * 8];
        p[0] = lo.x; p[1] = lo.y; p[2] = lo.z; p[3] = lo.w;
        p[4] = hi.x; p[5] = hi.y; p[6] = hi.z; p[7] = hi.w;
    }
    __syncthreads();
    if (tid < DIM) {
        float s = 0.f;
        #pragma unroll
        for (int i = 0; i < HW_HOP; ++i) s += s_part[i][tid];
        s_u[tid] = s * (1.0f / SLOTS);
    }
    __syncthreads();

    #pragma unroll
    for (int hop = 0; hop < 2; ++hop) {
        const __half* Mk = (hop == 0) ? M1 : M2;
        const __half* Mv = (hop == 0) ? M2 : M3;

        float ur[8];
        #pragma unroll
        for (int j = 0; j < 8; ++j) ur[j] = s_u[hl * 8 + j];

        #pragma unroll 5
        for (int k = 0; k < SL_HW; ++k) {
            const int slot = hw * SL_HW + k;
            uint4 v = reinterpret_cast<const uint4*>(Mk + (size_t)slot * DIM)[hl];
            float p = hw_sum(dot8(v, ur));
            if (hl == 0) s_score[slot] = p;
        }
        __syncthreads();

        float mx = -1e30f;
        for (int i = tid; i < SLOTS; i += HOP_T) mx = fmaxf(mx, s_score[i]);
        mx = warp_max(mx);
        if (lane == 0) s_red[w] = mx;
        __syncthreads();
        mx = s_red[0];
        #pragma unroll
        for (int i = 1; i < 16; ++i) mx = fmaxf(mx, s_red[i]);

        float ss = 0.f;
        for (int i = tid; i < SLOTS; i += HOP_T) {
            float e = __expf(s_score[i] - mx);
            s_score[i] = e;
            ss += e;
        }
        ss = warp_sum(ss);
        __syncthreads();
        if (lane == 0) s_red[w] = ss;
        __syncthreads();
        ss = 0.f;
        #pragma unroll
        for (int i = 0; i < 16; ++i) ss += s_red[i];
        const float inv = 1.0f / ss;

        {
            float4 lo = make_float4(0.f, 0.f, 0.f, 0.f), hi = lo;
            #pragma unroll 5
            for (int k = 0; k < SL_HW; ++k) {
                const int slot = hw * SL_HW + k;
                const float p = s_score[slot];
                uint4 v = reinterpret_cast<const uint4*>(Mv + (size_t)slot * DIM)[hl];
                float2 f;
                f = __half22float2(*reinterpret_cast<__half2*>(&v.x)); lo.x += p * f.x; lo.y += p * f.y;
                f = __half22float2(*reinterpret_cast<__half2*>(&v.y)); lo.z += p * f.x; lo.w += p * f.y;
                f = __half22float2(*reinterpret_cast<__half2*>(&v.z)); hi.x += p * f.x; hi.y += p * f.y;
                f = __half22float2(*reinterpret_cast<__half2*>(&v.w)); hi.z += p * f.x; hi.w += p * f.y;
            }
            float* p = &s_part[hw][hl * 8];
            p[0] = lo.x; p[1] = lo.y; p[2] = lo.z; p[3] = lo.w;
            p[4] = hi.x; p[5] = hi.y; p[6] = hi.z; p[7] = hi.w;
        }
        __syncthreads();

        if (tid < DIM) {
            float o = 0.f;
            #pragma unroll
            for (int i = 0; i < HW_HOP; ++i) o += s_part[i][tid];
            const float un = s_u[tid] + o * inv;
            if (hop == 0) s_u[tid] = un;
            else          out[b * DIM + tid] = un;
        }
        __syncthreads();
    }
}

// ---------------------------------------------------------------------------
// Launch with a forked stream so convert (DRAM-bound) overlaps gather
// (L2-bound) in the captured graph:
//   s2:   conv(T1) -e1-> conv(T2) -e2-> conv(T3) -e3
//   main: wait(e1) gather(T1); wait(e2) gather(T2); wait(e3) gather(T3); hops
// Streams/events are host objects (no device memory); created per call and
// leaked — kernel_launch is invoked only a couple of times.
// ---------------------------------------------------------------------------
extern "C" void kernel_launch(void* const* d_in, const int* in_sizes, int n_in,
                              void* d_out, int out_size)
{
    const float* C     = (const float*)d_in[0];  // [4, 50257, 128]
    const int*   story = (const int*)  d_in[1];  // [32, 512, 6]
    const int*   kb    = (const int*)  d_in[2];  // [32, 128, 64]
    float*       out   = (float*)d_out;          // [32, 128]

    cudaStream_t s2;
    cudaEvent_t  eF, e1, e2, e3;
    cudaStreamCreateWithFlags(&s2, cudaStreamNonBlocking);
    cudaEventCreateWithFlags(&eF, cudaEventDisableTiming);
    cudaEventCreateWithFlags(&e1, cudaEventDisableTiming);
    cudaEventCreateWithFlags(&e2, cudaEventDisableTiming);
    cudaEventCreateWithFlags(&e3, cudaEventDisableTiming);

    // fork s2 from the capture (main) stream
    cudaEventRecord(eF, 0);
    cudaStreamWaitEvent(s2, eF, 0);

    convert_kernel<<<CB_TAB, 256, 0, s2>>>(C, 0);
    cudaEventRecord(e1, s2);
    convert_kernel<<<CB_TAB, 256, 0, s2>>>(C, 1);
    cudaEventRecord(e2, s2);
    convert_kernel<<<CB_TAB, 256, 0, s2>>>(C, 2);
    cudaEventRecord(e3, s2);

    cudaStreamWaitEvent(0, e1, 0);
    gather_kernel<<<GBLK_TAB, 256>>>(story, kb, 0);
    cudaStreamWaitEvent(0, e2, 0);
    gather_kernel<<<GBLK_TAB, 256>>>(story, kb, 1);
    cudaStreamWaitEvent(0, e3, 0);   // also joins s2 back into the capture
    gather_kernel<<<GBLK_TAB, 256>>>(story, kb, 2);

    hops_kernel<<<BATCH, HOP_T>>>(out);
}